// round 1
// baseline (speedup 1.0000x reference)
#include <cuda_runtime.h>
#include <math.h>

#define B_ 2
#define N_ 2048
#define K_ 32
#define H_ 128
#define DFF_ 512
#define L_ 3
#define NNODE (B_*N_)          // 4096
#define NE (B_*N_*K_)          // 131072
#define EPSF 1e-6f

// ---------------- scratch (device globals; no allocation) ----------------
__device__ float g_t0[NE*H_];      // 64 MB
__device__ float g_t1[NE*H_];      // 64 MB
__device__ float g_hE[NE*H_];      // 64 MB
__device__ float g_Ebuf[NE*39];    // 20 MB
__device__ float g_hV[NNODE*H_];
__device__ float g_nA[NNODE*H_];
__device__ float g_nC[NNODE*H_];
__device__ float g_ff[NNODE*DFF_];
__device__ float g_dh[NNODE*H_];
__device__ float g_AD[NNODE*3];
__device__ float g_Of[NNODE*9];
__device__ int   g_Eidx[NE];
__device__ float g_Dnb[NE];

// ---------------- small helpers ----------------
__device__ __forceinline__ float sgnf(float x) { return (x > 0.f) ? 1.f : ((x < 0.f) ? -1.f : 0.f); }
__device__ __forceinline__ float clampc(float x) { return fminf(fmaxf(x, -1.f + EPSF), 1.f - EPSF); }

__device__ __forceinline__ float block_sum128(float v, float* red) {
    int o = threadIdx.x;
    red[o] = v; __syncthreads();
    #pragma unroll
    for (int s = 64; s > 0; s >>= 1) { if (o < s) red[o] += red[o + s]; __syncthreads(); }
    float r = red[0]; __syncthreads();
    return r;
}

// ---------------- kNN: per-row brute force + 32 min-extractions ----------------
__global__ void knn_kernel(const float* __restrict__ X, const float* __restrict__ mask) {
    __shared__ float sD[N_];
    __shared__ float red[256];
    __shared__ int   redi[256];
    int nf = blockIdx.x;           // b*N_ + i
    int b = nf / N_, i = nf % N_;
    int tid = threadIdx.x;
    float xi0 = X[nf*3+0], xi1 = X[nf*3+1], xi2 = X[nf*3+2];
    float mi = mask[nf];
    for (int j = tid; j < N_; j += 256) {
        float dx = xi0 - X[(b*N_+j)*3+0];
        float dy = xi1 - X[(b*N_+j)*3+1];
        float dz = xi2 - X[(b*N_+j)*3+2];
        float m2 = mi * mask[b*N_+j];
        sD[j] = m2 * sqrtf(dx*dx + dy*dy + dz*dz + EPSF);
    }
    __syncthreads();
    // row max (for mask adjustment)
    float mx = -3.4e38f;
    for (int j = tid; j < N_; j += 256) mx = fmaxf(mx, sD[j]);
    red[tid] = mx; __syncthreads();
    #pragma unroll
    for (int s = 128; s > 0; s >>= 1) { if (tid < s) red[tid] = fmaxf(red[tid], red[tid+s]); __syncthreads(); }
    float rowmax = red[0]; __syncthreads();
    for (int j = tid; j < N_; j += 256) {
        float m2 = mi * mask[b*N_+j];
        sD[j] = sD[j] + (1.f - m2) * rowmax;
    }
    __syncthreads();
    // extract K smallest (stable: ties -> smallest index)
    for (int k = 0; k < K_; k++) {
        float best = 3.4e38f; int bi = 0x7fffffff;
        for (int j = tid; j < N_; j += 256) {
            float v = sD[j];
            if (v < best || (v == best && j < bi)) { best = v; bi = j; }
        }
        red[tid] = best; redi[tid] = bi; __syncthreads();
        #pragma unroll
        for (int s = 128; s > 0; s >>= 1) {
            if (tid < s) {
                float v = red[tid+s]; int vi = redi[tid+s];
                if (v < red[tid] || (v == red[tid] && vi < redi[tid])) { red[tid] = v; redi[tid] = vi; }
            }
            __syncthreads();
        }
        if (tid == 0) {
            int e = nf*K_ + k;
            g_Eidx[e] = redi[0];
            g_Dnb[e]  = red[0];
            sD[redi[0]] = 3.4e38f;
        }
        __syncthreads();
    }
}

// ---------------- backbone frames + dihedral features ----------------
__global__ void frames_kernel(const float* __restrict__ X) {
    int nf = blockIdx.x*blockDim.x + threadIdx.x;
    if (nf >= NNODE) return;
    int n = nf % N_;
    float* ad = &g_AD[nf*3];
    float* of = &g_Of[nf*9];
    if (n < 1 || n > N_-3) {
        ad[0]=ad[1]=ad[2]=0.f;
        #pragma unroll
        for (int t=0;t<9;t++) of[t]=0.f;
        return;
    }
    float p[4][3];
    #pragma unroll
    for (int t=0;t<4;t++) { p[t][0]=X[(nf-1+t)*3+0]; p[t][1]=X[(nf-1+t)*3+1]; p[t][2]=X[(nf-1+t)*3+2]; }
    float u2[3], u1[3], u0[3];
    #pragma unroll
    for (int c=0;c<3;c++) { u2[c]=p[1][c]-p[0][c]; u1[c]=p[2][c]-p[1][c]; u0[c]=p[3][c]-p[2][c]; }
    auto normv = [](float* v) {
        float l = sqrtf(v[0]*v[0]+v[1]*v[1]+v[2]*v[2]);
        float il = 1.f / fmaxf(l, 1e-12f);
        v[0]*=il; v[1]*=il; v[2]*=il;
    };
    normv(u2); normv(u1); normv(u0);
    float n2[3] = { u2[1]*u1[2]-u2[2]*u1[1], u2[2]*u1[0]-u2[0]*u1[2], u2[0]*u1[1]-u2[1]*u1[0] };
    float n1[3] = { u1[1]*u0[2]-u1[2]*u0[1], u1[2]*u0[0]-u1[0]*u0[2], u1[0]*u0[1]-u1[1]*u0[0] };
    normv(n2); normv(n1);
    float cosA = clampc(-(u1[0]*u0[0]+u1[1]*u0[1]+u1[2]*u0[2]));
    float sinA = sqrtf(fmaxf(1.f - cosA*cosA, 0.f));
    float cosD = clampc(n2[0]*n1[0]+n2[1]*n1[1]+n2[2]*n1[2]);
    float sinD = sqrtf(fmaxf(1.f - cosD*cosD, 0.f));
    float sg = sgnf(u2[0]*n1[0]+u2[1]*n1[1]+u2[2]*n1[2]);
    ad[0] = cosA; ad[1] = sinA*cosD; ad[2] = sinA*sg*sinD;
    float o1[3] = { u2[0]-u1[0], u2[1]-u1[1], u2[2]-u1[2] };
    normv(o1);
    float cr[3] = { o1[1]*n2[2]-o1[2]*n2[1], o1[2]*n2[0]-o1[0]*n2[2], o1[0]*n2[1]-o1[1]*n2[0] };
    of[0]=o1[0]; of[1]=o1[1]; of[2]=o1[2];
    of[3]=n2[0]; of[4]=n2[1]; of[5]=n2[2];
    of[6]=cr[0]; of[7]=cr[1]; of[8]=cr[2];
}

// ---------------- node init: V = LN(AD@Wn+bn), hV = V@Wv+bv ----------------
__global__ void node_init_kernel(const float* __restrict__ Wn, const float* __restrict__ bn,
                                 const float* __restrict__ gn, const float* __restrict__ hn,
                                 const float* __restrict__ Wv, const float* __restrict__ bv) {
    __shared__ float sV[H_];
    __shared__ float red[H_];
    int n = blockIdx.x, o = threadIdx.x;
    float a0 = g_AD[n*3+0], a1 = g_AD[n*3+1], a2 = g_AD[n*3+2];
    float t = a0*Wn[o] + a1*Wn[H_+o] + a2*Wn[2*H_+o] + bn[o];
    float mu = block_sum128(t, red) * (1.f/H_);
    float dv = t - mu;
    float var = block_sum128(dv*dv, red) * (1.f/(H_-1));
    float y = gn[o]*dv/(sqrtf(var+EPSF)+EPSF) + hn[o];
    sV[o] = y; __syncthreads();
    float acc = bv[o];
    #pragma unroll 8
    for (int i = 0; i < H_; i++) acc += sV[i]*Wv[i*H_+o];
    g_hV[n*H_+o] = acc;
}

// ---------------- edge features (PE + RBF + orientation + quat) -> g_Ebuf ----------------
__global__ void edge_feat_kernel(const float* __restrict__ X) {
    int e = blockIdx.x*blockDim.x + threadIdx.x;
    if (e >= NE) return;
    int nf = e / K_;          // b*N_+n
    int n = nf % N_, b = nf / N_;
    int j = g_Eidx[e];
    float* E = &g_Ebuf[(size_t)e*39];
    // positional encoding
    float d = (float)(j - n);
    const float lc = -logf(10000.f) / 16.f;
    #pragma unroll
    for (int f = 0; f < 8; f++) {
        float freq = expf((2.f*f)*lc);
        float ang = d*freq;
        E[f]   = cosf(ang);
        E[8+f] = sinf(ang);
    }
    // RBF
    float D = g_Dnb[e];
    #pragma unroll
    for (int m = 0; m < 16; m++) {
        float mu = (20.f/15.f)*m;
        float t = (D - mu)*0.8f;
        E[16+m] = expf(-t*t);
    }
    // orientation
    float Om[9], Ob[9];
    #pragma unroll
    for (int t=0;t<9;t++) Om[t] = g_Of[nf*9+t];
    #pragma unroll
    for (int t=0;t<9;t++) Ob[t] = g_Of[(b*N_+j)*9+t];
    float dx0 = X[(b*N_+j)*3+0]-X[nf*3+0];
    float dx1 = X[(b*N_+j)*3+1]-X[nf*3+1];
    float dx2 = X[(b*N_+j)*3+2]-X[nf*3+2];
    float du[3];
    #pragma unroll
    for (int i=0;i<3;i++) du[i] = Om[i*3+0]*dx0 + Om[i*3+1]*dx1 + Om[i*3+2]*dx2;
    float l = sqrtf(du[0]*du[0]+du[1]*du[1]+du[2]*du[2]);
    float il = 1.f / fmaxf(l, 1e-12f);
    du[0]*=il; du[1]*=il; du[2]*=il;
    // R = Om^T @ Ob
    float R[3][3];
    #pragma unroll
    for (int i=0;i<3;i++)
        #pragma unroll
        for (int c=0;c<3;c++)
            R[i][c] = Om[0*3+i]*Ob[0*3+c] + Om[1*3+i]*Ob[1*3+c] + Om[2*3+i]*Ob[2*3+c];
    float Rxx=R[0][0], Ryy=R[1][1], Rzz=R[2][2];
    float m0 = 0.5f*sqrtf(fabsf(1.f + Rxx - Ryy - Rzz));
    float m1 = 0.5f*sqrtf(fabsf(1.f - Rxx + Ryy - Rzz));
    float m2 = 0.5f*sqrtf(fabsf(1.f - Rxx - Ryy + Rzz));
    float s0 = sgnf(R[2][1]-R[1][2]);
    float s1 = sgnf(R[0][2]-R[2][0]);
    float s2 = sgnf(R[1][0]-R[0][1]);
    float w  = sqrtf(fmaxf(1.f + Rxx + Ryy + Rzz, 0.f)) * 0.5f;
    float q[4] = { s0*m0, s1*m1, s2*m2, w };
    float ql = sqrtf(q[0]*q[0]+q[1]*q[1]+q[2]*q[2]+q[3]*q[3]);
    float iql = 1.f / fmaxf(ql, 1e-12f);
    E[32]=du[0]; E[33]=du[1]; E[34]=du[2];
    E[35]=q[0]*iql; E[36]=q[1]*iql; E[37]=q[2]*iql; E[38]=q[3]*iql;
}

// ---------------- generic tiled SGEMM: C = A(MxK) @ B(KxN) [+bias] [relu] ----------------
__global__ __launch_bounds__(256) void sgemm_kernel(const float* __restrict__ A, const float* __restrict__ B,
                                                    const float* __restrict__ bias, float* __restrict__ C,
                                                    int M, int N, int K, int relu) {
    __shared__ __align__(16) float As[8*128];
    __shared__ __align__(16) float Bs[8*128];
    int tid = threadIdx.x;
    int tx = tid & 15, ty = tid >> 4;
    int row0 = blockIdx.y * 128;
    int col0 = blockIdx.x * 128;
    float acc[8][8];
    #pragma unroll
    for (int i=0;i<8;i++)
        #pragma unroll
        for (int jj=0;jj<8;jj++) acc[i][jj]=0.f;
    for (int kk = 0; kk < K; kk += 8) {
        #pragma unroll
        for (int q = 0; q < 4; q++) {
            int el = tid*4 + q;
            int m = el >> 3, k = el & 7;
            float v = 0.f;
            if (kk + k < K) v = A[(size_t)(row0 + m)*K + kk + k];
            As[k*128 + m] = v;
        }
        #pragma unroll
        for (int q = 0; q < 4; q++) {
            int el = tid*4 + q;
            int k = el >> 7, nn = el & 127;
            float v = 0.f;
            if (kk + k < K) v = B[(size_t)(kk + k)*N + col0 + nn];
            Bs[k*128 + nn] = v;
        }
        __syncthreads();
        #pragma unroll
        for (int k = 0; k < 8; k++) {
            float a[8], bb[8];
            float4 a0 = *reinterpret_cast<const float4*>(&As[k*128 + ty*8]);
            float4 a1 = *reinterpret_cast<const float4*>(&As[k*128 + ty*8 + 4]);
            a[0]=a0.x;a[1]=a0.y;a[2]=a0.z;a[3]=a0.w;a[4]=a1.x;a[5]=a1.y;a[6]=a1.z;a[7]=a1.w;
            float4 b0 = *reinterpret_cast<const float4*>(&Bs[k*128 + tx*8]);
            float4 b1 = *reinterpret_cast<const float4*>(&Bs[k*128 + tx*8 + 4]);
            bb[0]=b0.x;bb[1]=b0.y;bb[2]=b0.z;bb[3]=b0.w;bb[4]=b1.x;bb[5]=b1.y;bb[6]=b1.z;bb[7]=b1.w;
            #pragma unroll
            for (int i=0;i<8;i++)
                #pragma unroll
                for (int jj=0;jj<8;jj++) acc[i][jj] += a[i]*bb[jj];
        }
        __syncthreads();
    }
    #pragma unroll
    for (int i=0;i<8;i++) {
        int r = row0 + ty*8 + i;
        #pragma unroll
        for (int jj=0;jj<8;jj++) {
            int c = col0 + tx*8 + jj;
            float v = acc[i][jj];
            if (bias) v += bias[c];
            if (relu) v = fmaxf(v, 0.f);
            C[(size_t)r*N + c] = v;
        }
    }
}

// ---------------- row layernorm (generic rows of width 128), warp per row ----------------
__global__ void ln_rows_kernel(float* __restrict__ x, const float* __restrict__ g, const float* __restrict__ h, int M) {
    int row = blockIdx.x*blockDim.y + threadIdx.y;
    if (row >= M) return;
    int lane = threadIdx.x;
    float v[4]; float s = 0.f;
    #pragma unroll
    for (int r=0;r<4;r++) { v[r] = x[(size_t)row*H_ + lane + r*32]; s += v[r]; }
    #pragma unroll
    for (int off=16;off>0;off>>=1) s += __shfl_xor_sync(0xffffffffu, s, off);
    float mu = s * (1.f/H_);
    float ss = 0.f;
    #pragma unroll
    for (int r=0;r<4;r++) { float d = v[r]-mu; ss += d*d; }
    #pragma unroll
    for (int off=16;off>0;off>>=1) ss += __shfl_xor_sync(0xffffffffu, ss, off);
    float inv = 1.f / (sqrtf(ss*(1.f/(H_-1)) + EPSF) + EPSF);
    #pragma unroll
    for (int r=0;r<4;r++) {
        int c = lane + r*32;
        x[(size_t)row*H_ + c] = g[c]*(v[r]-mu)*inv + h[c];
    }
}

// ---------------- combine: t0[e] = relu(t0[e] + nA[center] + nC[neighbor]) ----------------
__global__ void combine_kernel() {
    int idx = blockIdx.x*blockDim.x + threadIdx.x;
    if (idx >= NE*H_) return;
    int e = idx >> 7, o = idx & 127;
    int nf = e >> 5;                // center node (b*N_+n)
    int b = nf >> 11;               // N_=2048
    int j = g_Eidx[e];
    float v = g_t0[idx] + g_nA[nf*H_+o] + g_nC[(b*N_+j)*H_+o];
    g_t0[idx] = fmaxf(v, 0.f);
}

// ---------------- aggregate msgs + residual LN -> hV ----------------
__global__ void aggregate_kernel(const float* __restrict__ mask,
                                 const float* __restrict__ g0, const float* __restrict__ h0) {
    __shared__ float red[H_];
    int n = blockIdx.x, o = threadIdx.x;
    int b = n / N_;
    float mi = mask[n];
    float s = 0.f;
    for (int k = 0; k < K_; k++) {
        int e = n*K_ + k;
        int j = g_Eidx[e];
        float ma = mi * mask[b*N_+j];
        s += g_t0[(size_t)e*H_ + o] * ma;
    }
    float x = g_hV[n*H_+o] + s * (1.f/30.f);
    float mu = block_sum128(x, red) * (1.f/H_);
    float dv = x - mu;
    float var = block_sum128(dv*dv, red) * (1.f/(H_-1));
    g_hV[n*H_+o] = g0[o]*dv/(sqrtf(var+EPSF)+EPSF) + h0[o];
}

// ---------------- residual FFN LN + mask -> dst ----------------
__global__ void resln_kernel(float* __restrict__ dst, const float* __restrict__ mask,
                             const float* __restrict__ g1, const float* __restrict__ h1) {
    __shared__ float red[H_];
    int n = blockIdx.x, o = threadIdx.x;
    float x = g_hV[n*H_+o] + g_dh[n*H_+o];
    float mu = block_sum128(x, red) * (1.f/H_);
    float dv = x - mu;
    float var = block_sum128(dv*dv, red) * (1.f/(H_-1));
    float y = g1[o]*dv/(sqrtf(var+EPSF)+EPSF) + h1[o];
    dst[n*H_+o] = mask[n]*y;
}

// ---------------- host ----------------
static void sgemm(const float* A, const float* Bm, const float* bias, float* C,
                  int M, int N, int K, int relu) {
    dim3 grid(N/128, M/128);
    sgemm_kernel<<<grid, 256>>>(A, Bm, bias, C, M, N, K, relu);
}

extern "C" void kernel_launch(void* const* d_in, const int* in_sizes, int n_in,
                              void* d_out, int out_size) {
    const float* X    = (const float*)d_in[0];
    const float* mask = (const float*)d_in[1];
    const float* Wn   = (const float*)d_in[2];
    const float* bn   = (const float*)d_in[3];
    const float* gn   = (const float*)d_in[4];
    const float* hn   = (const float*)d_in[5];
    const float* We   = (const float*)d_in[6];
    const float* be   = (const float*)d_in[7];
    const float* ge   = (const float*)d_in[8];
    const float* he   = (const float*)d_in[9];
    const float* Wv   = (const float*)d_in[10];
    const float* bv   = (const float*)d_in[11];
    const float* Wq   = (const float*)d_in[12];
    const float* bq   = (const float*)d_in[13];
    const float* lW1  = (const float*)d_in[14];
    const float* lb1  = (const float*)d_in[15];
    const float* lW2  = (const float*)d_in[16];
    const float* lb2  = (const float*)d_in[17];
    const float* lW3  = (const float*)d_in[18];
    const float* lb3  = (const float*)d_in[19];
    const float* lWi  = (const float*)d_in[20];
    const float* lbi  = (const float*)d_in[21];
    const float* lWo  = (const float*)d_in[22];
    const float* lbo  = (const float*)d_in[23];
    const float* lg0  = (const float*)d_in[24];
    const float* lh0  = (const float*)d_in[25];
    const float* lg1  = (const float*)d_in[26];
    const float* lh1  = (const float*)d_in[27];

    float *t0, *t1, *hE, *hV, *nA, *nC, *ff, *dh, *Ebuf;
    cudaGetSymbolAddress((void**)&t0,   g_t0);
    cudaGetSymbolAddress((void**)&t1,   g_t1);
    cudaGetSymbolAddress((void**)&hE,   g_hE);
    cudaGetSymbolAddress((void**)&hV,   g_hV);
    cudaGetSymbolAddress((void**)&nA,   g_nA);
    cudaGetSymbolAddress((void**)&nC,   g_nC);
    cudaGetSymbolAddress((void**)&ff,   g_ff);
    cudaGetSymbolAddress((void**)&dh,   g_dh);
    cudaGetSymbolAddress((void**)&Ebuf, g_Ebuf);

    // Phase A: geometry + features
    knn_kernel<<<NNODE, 256>>>(X, mask);
    frames_kernel<<<(NNODE+255)/256, 256>>>(X);
    node_init_kernel<<<NNODE, 128>>>(Wn, bn, gn, hn, Wv, bv);
    edge_feat_kernel<<<(NE+255)/256, 256>>>(X);
    sgemm(Ebuf, We, be, t0, NE, H_, 39, 0);
    {
        dim3 blk(32, 8);
        ln_rows_kernel<<<(NE+7)/8, blk>>>(t0, ge, he, NE);
    }
    sgemm(t0, Wq, bq, hE, NE, H_, H_, 0);

    // Phase B: 3 message-passing layers
    for (int l = 0; l < L_; l++) {
        const float* W1 = lW1 + (size_t)l*384*H_;
        sgemm(hV, W1,            lb1 + l*H_, nA, NNODE, H_, H_, 0);   // center part (+b1)
        sgemm(hV, W1 + 256*H_,   nullptr,    nC, NNODE, H_, H_, 0);   // neighbor part
        sgemm(hE, W1 + 128*H_,   nullptr,    t0, NE,    H_, H_, 0);   // edge part
        combine_kernel<<<(NE*H_+255)/256, 256>>>();
        sgemm(t0, lW2 + (size_t)l*H_*H_, lb2 + l*H_, t1, NE, H_, H_, 1);
        sgemm(t1, lW3 + (size_t)l*H_*H_, lb3 + l*H_, t0, NE, H_, H_, 0);
        aggregate_kernel<<<NNODE, H_>>>(mask, lg0 + l*H_, lh0 + l*H_);
        sgemm(hV, lWi + (size_t)l*H_*DFF_, lbi + l*DFF_, ff, NNODE, DFF_, H_, 1);
        sgemm(ff, lWo + (size_t)l*DFF_*H_, lbo + l*H_,   dh, NNODE, H_, DFF_, 0);
        float* dst = (l == L_-1) ? (float*)d_out : hV;
        resln_kernel<<<NNODE, H_>>>(dst, mask, lg1 + l*H_, lh1 + l*H_);
    }
}

// round 2
// speedup vs baseline: 1.0104x; 1.0104x over previous
#include <cuda_runtime.h>
#include <math.h>

#define B_ 2
#define N_ 2048
#define K_ 32
#define H_ 128
#define DFF_ 512
#define L_ 3
#define NNODE (B_*N_)          // 4096
#define NE (B_*N_*K_)          // 131072
#define EPSF 1e-6f

// ---------------- scratch (device globals; no allocation) ----------------
__device__ float g_t0[NE*H_];      // 64 MB
__device__ float g_t1[NE*H_];      // 64 MB
__device__ float g_hE[NE*H_];      // 64 MB
__device__ float g_Ebuf[NE*39];    // 20 MB
__device__ float g_hV[NNODE*H_];
__device__ float g_nA[NNODE*H_];
__device__ float g_nC[NNODE*H_];
__device__ float g_ff[NNODE*DFF_];
__device__ float g_dh[NNODE*H_];
__device__ float g_AD[NNODE*3];
__device__ float g_Of[NNODE*9];
__device__ int   g_Eidx[NE];
__device__ float g_Dnb[NE];

// ---------------- small helpers ----------------
__device__ __forceinline__ float sgnf(float x) { return (x > 0.f) ? 1.f : ((x < 0.f) ? -1.f : 0.f); }
__device__ __forceinline__ float clampc(float x) { return fminf(fmaxf(x, -1.f + EPSF), 1.f - EPSF); }

__device__ __forceinline__ float block_sum128(float v, float* red) {
    int o = threadIdx.x;
    red[o] = v; __syncthreads();
    #pragma unroll
    for (int s = 64; s > 0; s >>= 1) { if (o < s) red[o] += red[o + s]; __syncthreads(); }
    float r = red[0]; __syncthreads();
    return r;
}

// ---------------- kNN: per-row brute force + 32 min-extractions ----------------
__global__ void knn_kernel(const float* __restrict__ X, const float* __restrict__ mask) {
    __shared__ float sD[N_];
    __shared__ float red[256];
    __shared__ int   redi[256];
    int nf = blockIdx.x;           // b*N_ + i
    int b = nf / N_, i = nf % N_;
    int tid = threadIdx.x;
    float xi0 = X[nf*3+0], xi1 = X[nf*3+1], xi2 = X[nf*3+2];
    float mi = mask[nf];
    for (int j = tid; j < N_; j += 256) {
        float dx = xi0 - X[(b*N_+j)*3+0];
        float dy = xi1 - X[(b*N_+j)*3+1];
        float dz = xi2 - X[(b*N_+j)*3+2];
        float m2 = mi * mask[b*N_+j];
        sD[j] = m2 * sqrtf(dx*dx + dy*dy + dz*dz + EPSF);
    }
    __syncthreads();
    // row max (for mask adjustment)
    float mx = -3.4e38f;
    for (int j = tid; j < N_; j += 256) mx = fmaxf(mx, sD[j]);
    red[tid] = mx; __syncthreads();
    #pragma unroll
    for (int s = 128; s > 0; s >>= 1) { if (tid < s) red[tid] = fmaxf(red[tid], red[tid+s]); __syncthreads(); }
    float rowmax = red[0]; __syncthreads();
    for (int j = tid; j < N_; j += 256) {
        float m2 = mi * mask[b*N_+j];
        sD[j] = sD[j] + (1.f - m2) * rowmax;
    }
    __syncthreads();
    // extract K smallest (stable: ties -> smallest index)
    for (int k = 0; k < K_; k++) {
        float best = 3.4e38f; int bi = 0x7fffffff;
        for (int j = tid; j < N_; j += 256) {
            float v = sD[j];
            if (v < best || (v == best && j < bi)) { best = v; bi = j; }
        }
        red[tid] = best; redi[tid] = bi; __syncthreads();
        #pragma unroll
        for (int s = 128; s > 0; s >>= 1) {
            if (tid < s) {
                float v = red[tid+s]; int vi = redi[tid+s];
                if (v < red[tid] || (v == red[tid] && vi < redi[tid])) { red[tid] = v; redi[tid] = vi; }
            }
            __syncthreads();
        }
        if (tid == 0) {
            int e = nf*K_ + k;
            g_Eidx[e] = redi[0];
            g_Dnb[e]  = red[0];
            sD[redi[0]] = 3.4e38f;
        }
        __syncthreads();
    }
}

// ---------------- backbone frames + dihedral features ----------------
__global__ void frames_kernel(const float* __restrict__ X) {
    int nf = blockIdx.x*blockDim.x + threadIdx.x;
    if (nf >= NNODE) return;
    int n = nf % N_;
    float* ad = &g_AD[nf*3];
    float* of = &g_Of[nf*9];
    if (n < 1 || n > N_-3) {
        ad[0]=ad[1]=ad[2]=0.f;
        #pragma unroll
        for (int t=0;t<9;t++) of[t]=0.f;
        return;
    }
    float p[4][3];
    #pragma unroll
    for (int t=0;t<4;t++) { p[t][0]=X[(nf-1+t)*3+0]; p[t][1]=X[(nf-1+t)*3+1]; p[t][2]=X[(nf-1+t)*3+2]; }
    float u2[3], u1[3], u0[3];
    #pragma unroll
    for (int c=0;c<3;c++) { u2[c]=p[1][c]-p[0][c]; u1[c]=p[2][c]-p[1][c]; u0[c]=p[3][c]-p[2][c]; }
    auto normv = [](float* v) {
        float l = sqrtf(v[0]*v[0]+v[1]*v[1]+v[2]*v[2]);
        float il = 1.f / fmaxf(l, 1e-12f);
        v[0]*=il; v[1]*=il; v[2]*=il;
    };
    normv(u2); normv(u1); normv(u0);
    float n2[3] = { u2[1]*u1[2]-u2[2]*u1[1], u2[2]*u1[0]-u2[0]*u1[2], u2[0]*u1[1]-u2[1]*u1[0] };
    float n1[3] = { u1[1]*u0[2]-u1[2]*u0[1], u1[2]*u0[0]-u1[0]*u0[2], u1[0]*u0[1]-u1[1]*u0[0] };
    normv(n2); normv(n1);
    float cosA = clampc(-(u1[0]*u0[0]+u1[1]*u0[1]+u1[2]*u0[2]));
    float sinA = sqrtf(fmaxf(1.f - cosA*cosA, 0.f));
    float cosD = clampc(n2[0]*n1[0]+n2[1]*n1[1]+n2[2]*n1[2]);
    float sinD = sqrtf(fmaxf(1.f - cosD*cosD, 0.f));
    float sg = sgnf(u2[0]*n1[0]+u2[1]*n1[1]+u2[2]*n1[2]);
    ad[0] = cosA; ad[1] = sinA*cosD; ad[2] = sinA*sg*sinD;
    float o1[3] = { u2[0]-u1[0], u2[1]-u1[1], u2[2]-u1[2] };
    normv(o1);
    float cr[3] = { o1[1]*n2[2]-o1[2]*n2[1], o1[2]*n2[0]-o1[0]*n2[2], o1[0]*n2[1]-o1[1]*n2[0] };
    of[0]=o1[0]; of[1]=o1[1]; of[2]=o1[2];
    of[3]=n2[0]; of[4]=n2[1]; of[5]=n2[2];
    of[6]=cr[0]; of[7]=cr[1]; of[8]=cr[2];
}

// ---------------- node init: V = LN(AD@Wn+bn), hV = V@Wv+bv ----------------
__global__ void node_init_kernel(const float* __restrict__ Wn, const float* __restrict__ bn,
                                 const float* __restrict__ gn, const float* __restrict__ hn,
                                 const float* __restrict__ Wv, const float* __restrict__ bv) {
    __shared__ float sV[H_];
    __shared__ float red[H_];
    int n = blockIdx.x, o = threadIdx.x;
    float a0 = g_AD[n*3+0], a1 = g_AD[n*3+1], a2 = g_AD[n*3+2];
    float t = a0*Wn[o] + a1*Wn[H_+o] + a2*Wn[2*H_+o] + bn[o];
    float mu = block_sum128(t, red) * (1.f/H_);
    float dv = t - mu;
    float var = block_sum128(dv*dv, red) * (1.f/(H_-1));
    float y = gn[o]*dv/(sqrtf(var+EPSF)+EPSF) + hn[o];
    sV[o] = y; __syncthreads();
    float acc = bv[o];
    #pragma unroll 8
    for (int i = 0; i < H_; i++) acc += sV[i]*Wv[i*H_+o];
    g_hV[n*H_+o] = acc;
}

// ---------------- edge features (PE + RBF + orientation + quat) -> g_Ebuf ----------------
__global__ void edge_feat_kernel(const float* __restrict__ X) {
    int e = blockIdx.x*blockDim.x + threadIdx.x;
    if (e >= NE) return;
    int nf = e / K_;          // b*N_+n
    int n = nf % N_, b = nf / N_;
    int j = g_Eidx[e];
    float* E = &g_Ebuf[(size_t)e*39];
    // positional encoding
    float d = (float)(j - n);
    const float lc = -logf(10000.f) / 16.f;
    #pragma unroll
    for (int f = 0; f < 8; f++) {
        float freq = expf((2.f*f)*lc);
        float ang = d*freq;
        E[f]   = cosf(ang);
        E[8+f] = sinf(ang);
    }
    // RBF
    float D = g_Dnb[e];
    #pragma unroll
    for (int m = 0; m < 16; m++) {
        float mu = (20.f/15.f)*m;
        float t = (D - mu)*0.8f;
        E[16+m] = expf(-t*t);
    }
    // orientation
    float Om[9], Ob[9];
    #pragma unroll
    for (int t=0;t<9;t++) Om[t] = g_Of[nf*9+t];
    #pragma unroll
    for (int t=0;t<9;t++) Ob[t] = g_Of[(b*N_+j)*9+t];
    float dx0 = X[(b*N_+j)*3+0]-X[nf*3+0];
    float dx1 = X[(b*N_+j)*3+1]-X[nf*3+1];
    float dx2 = X[(b*N_+j)*3+2]-X[nf*3+2];
    float du[3];
    #pragma unroll
    for (int i=0;i<3;i++) du[i] = Om[i*3+0]*dx0 + Om[i*3+1]*dx1 + Om[i*3+2]*dx2;
    float l = sqrtf(du[0]*du[0]+du[1]*du[1]+du[2]*du[2]);
    float il = 1.f / fmaxf(l, 1e-12f);
    du[0]*=il; du[1]*=il; du[2]*=il;
    // R = Om^T @ Ob
    float R[3][3];
    #pragma unroll
    for (int i=0;i<3;i++)
        #pragma unroll
        for (int c=0;c<3;c++)
            R[i][c] = Om[0*3+i]*Ob[0*3+c] + Om[1*3+i]*Ob[1*3+c] + Om[2*3+i]*Ob[2*3+c];
    float Rxx=R[0][0], Ryy=R[1][1], Rzz=R[2][2];
    float m0 = 0.5f*sqrtf(fabsf(1.f + Rxx - Ryy - Rzz));
    float m1 = 0.5f*sqrtf(fabsf(1.f - Rxx + Ryy - Rzz));
    float m2 = 0.5f*sqrtf(fabsf(1.f - Rxx - Ryy + Rzz));
    float s0 = sgnf(R[2][1]-R[1][2]);
    float s1 = sgnf(R[0][2]-R[2][0]);
    float s2 = sgnf(R[1][0]-R[0][1]);
    float w  = sqrtf(fmaxf(1.f + Rxx + Ryy + Rzz, 0.f)) * 0.5f;
    float q[4] = { s0*m0, s1*m1, s2*m2, w };
    float ql = sqrtf(q[0]*q[0]+q[1]*q[1]+q[2]*q[2]+q[3]*q[3]);
    float iql = 1.f / fmaxf(ql, 1e-12f);
    E[32]=du[0]; E[33]=du[1]; E[34]=du[2];
    E[35]=q[0]*iql; E[36]=q[1]*iql; E[37]=q[2]*iql; E[38]=q[3]*iql;
}

// ---------------- generic tiled SGEMM: C = A(MxK) @ B(KxN) [+bias] [relu] ----------------
__global__ __launch_bounds__(256) void sgemm_kernel(const float* __restrict__ A, const float* __restrict__ B,
                                                    const float* __restrict__ bias, float* __restrict__ C,
                                                    int M, int N, int K, int relu) {
    __shared__ __align__(16) float As[8*128];
    __shared__ __align__(16) float Bs[8*128];
    int tid = threadIdx.x;
    int tx = tid & 15, ty = tid >> 4;
    int row0 = blockIdx.y * 128;
    int col0 = blockIdx.x * 128;
    float acc[8][8];
    #pragma unroll
    for (int i=0;i<8;i++)
        #pragma unroll
        for (int jj=0;jj<8;jj++) acc[i][jj]=0.f;
    for (int kk = 0; kk < K; kk += 8) {
        #pragma unroll
        for (int q = 0; q < 4; q++) {
            int el = tid*4 + q;
            int m = el >> 3, k = el & 7;
            float v = 0.f;
            if (kk + k < K) v = A[(size_t)(row0 + m)*K + kk + k];
            As[k*128 + m] = v;
        }
        #pragma unroll
        for (int q = 0; q < 4; q++) {
            int el = tid*4 + q;
            int k = el >> 7, nn = el & 127;
            float v = 0.f;
            if (kk + k < K) v = B[(size_t)(kk + k)*N + col0 + nn];
            Bs[k*128 + nn] = v;
        }
        __syncthreads();
        #pragma unroll
        for (int k = 0; k < 8; k++) {
            float a[8], bb[8];
            float4 a0 = *reinterpret_cast<const float4*>(&As[k*128 + ty*8]);
            float4 a1 = *reinterpret_cast<const float4*>(&As[k*128 + ty*8 + 4]);
            a[0]=a0.x;a[1]=a0.y;a[2]=a0.z;a[3]=a0.w;a[4]=a1.x;a[5]=a1.y;a[6]=a1.z;a[7]=a1.w;
            float4 b0 = *reinterpret_cast<const float4*>(&Bs[k*128 + tx*8]);
            float4 b1 = *reinterpret_cast<const float4*>(&Bs[k*128 + tx*8 + 4]);
            bb[0]=b0.x;bb[1]=b0.y;bb[2]=b0.z;bb[3]=b0.w;bb[4]=b1.x;bb[5]=b1.y;bb[6]=b1.z;bb[7]=b1.w;
            #pragma unroll
            for (int i=0;i<8;i++)
                #pragma unroll
                for (int jj=0;jj<8;jj++) acc[i][jj] += a[i]*bb[jj];
        }
        __syncthreads();
    }
    #pragma unroll
    for (int i=0;i<8;i++) {
        int r = row0 + ty*8 + i;
        #pragma unroll
        for (int jj=0;jj<8;jj++) {
            int c = col0 + tx*8 + jj;
            float v = acc[i][jj];
            if (bias) v += bias[c];
            if (relu) v = fmaxf(v, 0.f);
            C[(size_t)r*N + c] = v;
        }
    }
}

// ---------------- row layernorm (generic rows of width 128), warp per row ----------------
__global__ void ln_rows_kernel(float* __restrict__ x, const float* __restrict__ g, const float* __restrict__ h, int M) {
    int row = blockIdx.x*blockDim.y + threadIdx.y;
    if (row >= M) return;
    int lane = threadIdx.x;
    float v[4]; float s = 0.f;
    #pragma unroll
    for (int r=0;r<4;r++) { v[r] = x[(size_t)row*H_ + lane + r*32]; s += v[r]; }
    #pragma unroll
    for (int off=16;off>0;off>>=1) s += __shfl_xor_sync(0xffffffffu, s, off);
    float mu = s * (1.f/H_);
    float ss = 0.f;
    #pragma unroll
    for (int r=0;r<4;r++) { float d = v[r]-mu; ss += d*d; }
    #pragma unroll
    for (int off=16;off>0;off>>=1) ss += __shfl_xor_sync(0xffffffffu, ss, off);
    float inv = 1.f / (sqrtf(ss*(1.f/(H_-1)) + EPSF) + EPSF);
    #pragma unroll
    for (int r=0;r<4;r++) {
        int c = lane + r*32;
        x[(size_t)row*H_ + c] = g[c]*(v[r]-mu)*inv + h[c];
    }
}

// ---------------- combine: t0[e] = relu(t0[e] + nA[center] + nC[neighbor]) ----------------
__global__ void combine_kernel() {
    int idx = blockIdx.x*blockDim.x + threadIdx.x;
    if (idx >= NE*H_) return;
    int e = idx >> 7, o = idx & 127;
    int nf = e >> 5;                // center node (b*N_+n)
    int b = nf >> 11;               // N_=2048
    int j = g_Eidx[e];
    float v = g_t0[idx] + g_nA[nf*H_+o] + g_nC[(b*N_+j)*H_+o];
    g_t0[idx] = fmaxf(v, 0.f);
}

// ---------------- aggregate msgs + residual LN -> hV ----------------
__global__ void aggregate_kernel(const float* __restrict__ mask,
                                 const float* __restrict__ g0, const float* __restrict__ h0) {
    __shared__ float red[H_];
    int n = blockIdx.x, o = threadIdx.x;
    int b = n / N_;
    float mi = mask[n];
    float s = 0.f;
    for (int k = 0; k < K_; k++) {
        int e = n*K_ + k;
        int j = g_Eidx[e];
        float ma = mi * mask[b*N_+j];
        s += g_t0[(size_t)e*H_ + o] * ma;
    }
    float x = g_hV[n*H_+o] + s * (1.f/30.f);
    float mu = block_sum128(x, red) * (1.f/H_);
    float dv = x - mu;
    float var = block_sum128(dv*dv, red) * (1.f/(H_-1));
    g_hV[n*H_+o] = g0[o]*dv/(sqrtf(var+EPSF)+EPSF) + h0[o];
}

// ---------------- residual FFN LN + mask -> dst ----------------
__global__ void resln_kernel(float* __restrict__ dst, const float* __restrict__ mask,
                             const float* __restrict__ g1, const float* __restrict__ h1) {
    __shared__ float red[H_];
    int n = blockIdx.x, o = threadIdx.x;
    float x = g_hV[n*H_+o] + g_dh[n*H_+o];
    float mu = block_sum128(x, red) * (1.f/H_);
    float dv = x - mu;
    float var = block_sum128(dv*dv, red) * (1.f/(H_-1));
    float y = g1[o]*dv/(sqrtf(var+EPSF)+EPSF) + h1[o];
    dst[n*H_+o] = mask[n]*y;
}

// ---------------- host ----------------
static void sgemm(const float* A, const float* Bm, const float* bias, float* C,
                  int M, int N, int K, int relu) {
    dim3 grid(N/128, M/128);
    sgemm_kernel<<<grid, 256>>>(A, Bm, bias, C, M, N, K, relu);
}

extern "C" void kernel_launch(void* const* d_in, const int* in_sizes, int n_in,
                              void* d_out, int out_size) {
    const float* X    = (const float*)d_in[0];
    const float* mask = (const float*)d_in[1];
    const float* Wn   = (const float*)d_in[2];
    const float* bn   = (const float*)d_in[3];
    const float* gn   = (const float*)d_in[4];
    const float* hn   = (const float*)d_in[5];
    const float* We   = (const float*)d_in[6];
    const float* be   = (const float*)d_in[7];
    const float* ge   = (const float*)d_in[8];
    const float* he   = (const float*)d_in[9];
    const float* Wv   = (const float*)d_in[10];
    const float* bv   = (const float*)d_in[11];
    const float* Wq   = (const float*)d_in[12];
    const float* bq   = (const float*)d_in[13];
    const float* lW1  = (const float*)d_in[14];
    const float* lb1  = (const float*)d_in[15];
    const float* lW2  = (const float*)d_in[16];
    const float* lb2  = (const float*)d_in[17];
    const float* lW3  = (const float*)d_in[18];
    const float* lb3  = (const float*)d_in[19];
    const float* lWi  = (const float*)d_in[20];
    const float* lbi  = (const float*)d_in[21];
    const float* lWo  = (const float*)d_in[22];
    const float* lbo  = (const float*)d_in[23];
    const float* lg0  = (const float*)d_in[24];
    const float* lh0  = (const float*)d_in[25];
    const float* lg1  = (const float*)d_in[26];
    const float* lh1  = (const float*)d_in[27];

    float *t0, *t1, *hE, *hV, *nA, *nC, *ff, *dh, *Ebuf;
    cudaGetSymbolAddress((void**)&t0,   g_t0);
    cudaGetSymbolAddress((void**)&t1,   g_t1);
    cudaGetSymbolAddress((void**)&hE,   g_hE);
    cudaGetSymbolAddress((void**)&hV,   g_hV);
    cudaGetSymbolAddress((void**)&nA,   g_nA);
    cudaGetSymbolAddress((void**)&nC,   g_nC);
    cudaGetSymbolAddress((void**)&ff,   g_ff);
    cudaGetSymbolAddress((void**)&dh,   g_dh);
    cudaGetSymbolAddress((void**)&Ebuf, g_Ebuf);

    // Phase A: geometry + features
    knn_kernel<<<NNODE, 256>>>(X, mask);
    frames_kernel<<<(NNODE+255)/256, 256>>>(X);
    node_init_kernel<<<NNODE, 128>>>(Wn, bn, gn, hn, Wv, bv);
    edge_feat_kernel<<<(NE+255)/256, 256>>>(X);
    sgemm(Ebuf, We, be, t0, NE, H_, 39, 0);
    {
        dim3 blk(32, 8);
        ln_rows_kernel<<<(NE+7)/8, blk>>>(t0, ge, he, NE);
    }
    sgemm(t0, Wq, bq, hE, NE, H_, H_, 0);

    // Phase B: 3 message-passing layers
    for (int l = 0; l < L_; l++) {
        const float* W1 = lW1 + (size_t)l*384*H_;
        sgemm(hV, W1,            lb1 + l*H_, nA, NNODE, H_, H_, 0);   // center part (+b1)
        sgemm(hV, W1 + 256*H_,   nullptr,    nC, NNODE, H_, H_, 0);   // neighbor part
        sgemm(hE, W1 + 128*H_,   nullptr,    t0, NE,    H_, H_, 0);   // edge part
        combine_kernel<<<(NE*H_+255)/256, 256>>>();
        sgemm(t0, lW2 + (size_t)l*H_*H_, lb2 + l*H_, t1, NE, H_, H_, 1);
        sgemm(t1, lW3 + (size_t)l*H_*H_, lb3 + l*H_, t0, NE, H_, H_, 0);
        aggregate_kernel<<<NNODE, H_>>>(mask, lg0 + l*H_, lh0 + l*H_);
        sgemm(hV, lWi + (size_t)l*H_*DFF_, lbi + l*DFF_, ff, NNODE, DFF_, H_, 1);
        sgemm(ff, lWo + (size_t)l*DFF_*H_, lbo + l*H_,   dh, NNODE, H_, DFF_, 0);
        float* dst = (l == L_-1) ? (float*)d_out : hV;
        resln_kernel<<<NNODE, H_>>>(dst, mask, lg1 + l*H_, lh1 + l*H_);
    }
}

// round 4
// speedup vs baseline: 2.3828x; 2.3583x over previous
#include <cuda_runtime.h>
#include <cuda_bf16.h>
#include <math.h>
#include <stdint.h>

#define B_ 2
#define N_ 2048
#define K_ 32
#define H_ 128
#define DFF_ 512
#define L_ 3
#define NNODE (B_*N_)
#define NE (B_*N_*K_)
#define EPSF 1e-6f

// weight area offsets (elements)
#define OFF_WE 0
#define OFF_WQ 8192
#define OFF_L0 24576
#define LSTRIDE 212992
#define OW1A 0
#define OW1E 16384
#define OW1C 32768
#define OW2  49152
#define OW3  65536
#define OWI  81920
#define OWO  147456
#define WTOT (24576 + 3*212992)

// ---------------- device scratch ----------------
__device__ float g_t0[(size_t)NE*H_];
__device__ float g_t1[(size_t)NE*H_];
__device__ float g_hE[(size_t)NE*H_];
__device__ float g_Ebuf[(size_t)NE*64];
__device__ float g_hV[NNODE*H_];
__device__ float g_nA[NNODE*H_];
__device__ float g_nC[NNODE*H_];
__device__ float g_ff[NNODE*DFF_];
__device__ float g_dh[NNODE*H_];
__device__ float g_AD[NNODE*3];
__device__ float g_Of[NNODE*9];
__device__ int   g_Eidx[NE];
__device__ float g_Dnb[NE];
__device__ __nv_bfloat16 g_wh[WTOT];
__device__ __nv_bfloat16 g_wl[WTOT];

__device__ __forceinline__ float sgnf(float x) { return (x > 0.f) ? 1.f : ((x < 0.f) ? -1.f : 0.f); }
__device__ __forceinline__ float clampc(float x) { return fminf(fmaxf(x, -1.f + EPSF), 1.f - EPSF); }

__device__ __forceinline__ float block_sum128(float v, float* red) {
    int o = threadIdx.x;
    red[o] = v; __syncthreads();
    #pragma unroll
    for (int s = 64; s > 0; s >>= 1) { if (o < s) red[o] += red[o + s]; __syncthreads(); }
    float r = red[0]; __syncthreads();
    return r;
}

// ---------------- kNN ----------------
__global__ void knn_kernel(const float* __restrict__ X, const float* __restrict__ mask) {
    __shared__ float sD[N_];
    __shared__ float red[256];
    __shared__ int   redi[256];
    int nf = blockIdx.x;
    int b = nf / N_;
    int tid = threadIdx.x;
    float xi0 = X[nf*3+0], xi1 = X[nf*3+1], xi2 = X[nf*3+2];
    float mi = mask[nf];
    for (int j = tid; j < N_; j += 256) {
        float dx = xi0 - X[(b*N_+j)*3+0];
        float dy = xi1 - X[(b*N_+j)*3+1];
        float dz = xi2 - X[(b*N_+j)*3+2];
        float m2 = mi * mask[b*N_+j];
        sD[j] = m2 * sqrtf(dx*dx + dy*dy + dz*dz + EPSF);
    }
    __syncthreads();
    float mx = -3.4e38f;
    for (int j = tid; j < N_; j += 256) mx = fmaxf(mx, sD[j]);
    red[tid] = mx; __syncthreads();
    #pragma unroll
    for (int s = 128; s > 0; s >>= 1) { if (tid < s) red[tid] = fmaxf(red[tid], red[tid+s]); __syncthreads(); }
    float rowmax = red[0]; __syncthreads();
    for (int j = tid; j < N_; j += 256) {
        float m2 = mi * mask[b*N_+j];
        sD[j] = sD[j] + (1.f - m2) * rowmax;
    }
    __syncthreads();
    for (int k = 0; k < K_; k++) {
        float best = 3.4e38f; int bi = 0x7fffffff;
        for (int j = tid; j < N_; j += 256) {
            float v = sD[j];
            if (v < best || (v == best && j < bi)) { best = v; bi = j; }
        }
        red[tid] = best; redi[tid] = bi; __syncthreads();
        #pragma unroll
        for (int s = 128; s > 0; s >>= 1) {
            if (tid < s) {
                float v = red[tid+s]; int vi = redi[tid+s];
                if (v < red[tid] || (v == red[tid] && vi < redi[tid])) { red[tid] = v; redi[tid] = vi; }
            }
            __syncthreads();
        }
        if (tid == 0) {
            int e = nf*K_ + k;
            g_Eidx[e] = redi[0];
            g_Dnb[e]  = red[0];
            sD[redi[0]] = 3.4e38f;
        }
        __syncthreads();
    }
}

// ---------------- frames ----------------
__global__ void frames_kernel(const float* __restrict__ X) {
    int nf = blockIdx.x*blockDim.x + threadIdx.x;
    if (nf >= NNODE) return;
    int n = nf % N_;
    float* ad = &g_AD[nf*3];
    float* of = &g_Of[nf*9];
    if (n < 1 || n > N_-3) {
        ad[0]=ad[1]=ad[2]=0.f;
        #pragma unroll
        for (int t=0;t<9;t++) of[t]=0.f;
        return;
    }
    float p[4][3];
    #pragma unroll
    for (int t=0;t<4;t++) { p[t][0]=X[(nf-1+t)*3+0]; p[t][1]=X[(nf-1+t)*3+1]; p[t][2]=X[(nf-1+t)*3+2]; }
    float u2[3], u1[3], u0[3];
    #pragma unroll
    for (int c=0;c<3;c++) { u2[c]=p[1][c]-p[0][c]; u1[c]=p[2][c]-p[1][c]; u0[c]=p[3][c]-p[2][c]; }
    auto normv = [](float* v) {
        float l = sqrtf(v[0]*v[0]+v[1]*v[1]+v[2]*v[2]);
        float il = 1.f / fmaxf(l, 1e-12f);
        v[0]*=il; v[1]*=il; v[2]*=il;
    };
    normv(u2); normv(u1); normv(u0);
    float n2[3] = { u2[1]*u1[2]-u2[2]*u1[1], u2[2]*u1[0]-u2[0]*u1[2], u2[0]*u1[1]-u2[1]*u1[0] };
    float n1[3] = { u1[1]*u0[2]-u1[2]*u0[1], u1[2]*u0[0]-u1[0]*u0[2], u1[0]*u0[1]-u1[1]*u0[0] };
    normv(n2); normv(n1);
    float cosA = clampc(-(u1[0]*u0[0]+u1[1]*u0[1]+u1[2]*u0[2]));
    float sinA = sqrtf(fmaxf(1.f - cosA*cosA, 0.f));
    float cosD = clampc(n2[0]*n1[0]+n2[1]*n1[1]+n2[2]*n1[2]);
    float sinD = sqrtf(fmaxf(1.f - cosD*cosD, 0.f));
    float sg = sgnf(u2[0]*n1[0]+u2[1]*n1[1]+u2[2]*n1[2]);
    ad[0] = cosA; ad[1] = sinA*cosD; ad[2] = sinA*sg*sinD;
    float o1[3] = { u2[0]-u1[0], u2[1]-u1[1], u2[2]-u1[2] };
    normv(o1);
    float cr[3] = { o1[1]*n2[2]-o1[2]*n2[1], o1[2]*n2[0]-o1[0]*n2[2], o1[0]*n2[1]-o1[1]*n2[0] };
    of[0]=o1[0]; of[1]=o1[1]; of[2]=o1[2];
    of[3]=n2[0]; of[4]=n2[1]; of[5]=n2[2];
    of[6]=cr[0]; of[7]=cr[1]; of[8]=cr[2];
}

// ---------------- node init ----------------
__global__ void node_init_kernel(const float* __restrict__ Wn, const float* __restrict__ bn,
                                 const float* __restrict__ gn, const float* __restrict__ hn,
                                 const float* __restrict__ Wv, const float* __restrict__ bv) {
    __shared__ float sV[H_];
    __shared__ float red[H_];
    int n = blockIdx.x, o = threadIdx.x;
    float a0 = g_AD[n*3+0], a1 = g_AD[n*3+1], a2 = g_AD[n*3+2];
    float t = a0*Wn[o] + a1*Wn[H_+o] + a2*Wn[2*H_+o] + bn[o];
    float mu = block_sum128(t, red) * (1.f/H_);
    float dv = t - mu;
    float var = block_sum128(dv*dv, red) * (1.f/(H_-1));
    float y = gn[o]*dv/(sqrtf(var+EPSF)+EPSF) + hn[o];
    sV[o] = y; __syncthreads();
    float acc = bv[o];
    #pragma unroll 8
    for (int i = 0; i < H_; i++) acc += sV[i]*Wv[i*H_+o];
    g_hV[n*H_+o] = acc;
}

// ---------------- edge features (stride 64, zero-padded) ----------------
__global__ void edge_feat_kernel(const float* __restrict__ X) {
    int e = blockIdx.x*blockDim.x + threadIdx.x;
    if (e >= NE) return;
    int nf = e / K_;
    int n = nf % N_, b = nf / N_;
    int j = g_Eidx[e];
    float* E = &g_Ebuf[(size_t)e*64];
    float d = (float)(j - n);
    const float lc = -logf(10000.f) / 16.f;
    #pragma unroll
    for (int f = 0; f < 8; f++) {
        float freq = expf((2.f*f)*lc);
        float ang = d*freq;
        E[f]   = cosf(ang);
        E[8+f] = sinf(ang);
    }
    float D = g_Dnb[e];
    #pragma unroll
    for (int m = 0; m < 16; m++) {
        float mu = (20.f/15.f)*m;
        float t = (D - mu)*0.8f;
        E[16+m] = expf(-t*t);
    }
    float Om[9], Ob[9];
    #pragma unroll
    for (int t=0;t<9;t++) Om[t] = g_Of[nf*9+t];
    #pragma unroll
    for (int t=0;t<9;t++) Ob[t] = g_Of[(b*N_+j)*9+t];
    float dx0 = X[(b*N_+j)*3+0]-X[nf*3+0];
    float dx1 = X[(b*N_+j)*3+1]-X[nf*3+1];
    float dx2 = X[(b*N_+j)*3+2]-X[nf*3+2];
    float du[3];
    #pragma unroll
    for (int i=0;i<3;i++) du[i] = Om[i*3+0]*dx0 + Om[i*3+1]*dx1 + Om[i*3+2]*dx2;
    float l = sqrtf(du[0]*du[0]+du[1]*du[1]+du[2]*du[2]);
    float il = 1.f / fmaxf(l, 1e-12f);
    du[0]*=il; du[1]*=il; du[2]*=il;
    float R[3][3];
    #pragma unroll
    for (int i=0;i<3;i++)
        #pragma unroll
        for (int c=0;c<3;c++)
            R[i][c] = Om[0*3+i]*Ob[0*3+c] + Om[1*3+i]*Ob[1*3+c] + Om[2*3+i]*Ob[2*3+c];
    float Rxx=R[0][0], Ryy=R[1][1], Rzz=R[2][2];
    float m0 = 0.5f*sqrtf(fabsf(1.f + Rxx - Ryy - Rzz));
    float m1 = 0.5f*sqrtf(fabsf(1.f - Rxx + Ryy - Rzz));
    float m2 = 0.5f*sqrtf(fabsf(1.f - Rxx - Ryy + Rzz));
    float s0 = sgnf(R[2][1]-R[1][2]);
    float s1 = sgnf(R[0][2]-R[2][0]);
    float s2 = sgnf(R[1][0]-R[0][1]);
    float w  = sqrtf(fmaxf(1.f + Rxx + Ryy + Rzz, 0.f)) * 0.5f;
    float q[4] = { s0*m0, s1*m1, s2*m2, w };
    float ql = sqrtf(q[0]*q[0]+q[1]*q[1]+q[2]*q[2]+q[3]*q[3]);
    float iql = 1.f / fmaxf(ql, 1e-12f);
    E[32]=du[0]; E[33]=du[1]; E[34]=du[2];
    E[35]=q[0]*iql; E[36]=q[1]*iql; E[37]=q[2]*iql; E[38]=q[3]*iql;
    #pragma unroll
    for (int t = 39; t < 64; t++) E[t] = 0.f;
}

// ---------------- weight prep: transpose + hi/lo bf16 split -> [n][k] ----------------
__global__ void prep_w(const float* __restrict__ W, __nv_bfloat16* __restrict__ hi,
                       __nv_bfloat16* __restrict__ lo, int Ksrc, int N, int Kpad) {
    int idx = blockIdx.x*256 + threadIdx.x;
    if (idx >= N*Kpad) return;
    int n = idx / Kpad, k = idx - n*Kpad;
    float v = (k < Ksrc) ? W[(size_t)k*N + n] : 0.f;
    __nv_bfloat16 bh = __float2bfloat16(v);
    hi[idx] = bh;
    lo[idx] = __float2bfloat16(v - __bfloat162float(bh));
}

// ---------------- split-bf16 mma.sync GEMM: C(MxN) = A(MxK fp32) @ Bt(NxK bf16 hi/lo) ----------------
#define STR 40    // smem row stride in bf16 elements
#define STRW 20   // in 32-bit words

__device__ __forceinline__ void mma16816(float* d, const uint32_t* a, uint32_t b0, uint32_t b1) {
    asm volatile(
        "mma.sync.aligned.m16n8k16.row.col.f32.bf16.bf16.f32 "
        "{%0,%1,%2,%3}, {%4,%5,%6,%7}, {%8,%9}, {%0,%1,%2,%3};"
        : "+f"(d[0]), "+f"(d[1]), "+f"(d[2]), "+f"(d[3])
        : "r"(a[0]), "r"(a[1]), "r"(a[2]), "r"(a[3]), "r"(b0), "r"(b1));
}

__global__ __launch_bounds__(256, 2) void mma_gemm(
    const float* __restrict__ A, const __nv_bfloat16* __restrict__ Bhi,
    const __nv_bfloat16* __restrict__ Blo, const float* __restrict__ bias,
    float* __restrict__ C, int K, int ldc, int mode, int relu)
{
    __shared__ __nv_bfloat16 sAh[128*STR];
    __shared__ __nv_bfloat16 sAl[128*STR];
    __shared__ __nv_bfloat16 sBh[128*STR];
    __shared__ __nv_bfloat16 sBl[128*STR];
    int tid = threadIdx.x, lane = tid & 31, w = tid >> 5;
    int wm = w & 3, wn = w >> 2;
    int row0 = blockIdx.y*128, colb = blockIdx.x*128;
    int g = lane >> 2, t = lane & 3;

    float acc[2][8][4];
    #pragma unroll
    for (int mt=0;mt<2;mt++)
        #pragma unroll
        for (int nt=0;nt<8;nt++)
            #pragma unroll
            for (int q=0;q<4;q++) acc[mt][nt][q] = 0.f;

    const int nk = K >> 5;
    for (int kc = 0; kc < nk; kc++) {
        // A: 128 x 32 fp32 -> split hi/lo
        #pragma unroll
        for (int i = 0; i < 4; i++) {
            int idx = tid + i*256;
            int r = idx >> 3, kq = (idx & 7) * 4;
            float4 va = *reinterpret_cast<const float4*>(A + (size_t)(row0+r)*K + kc*32 + kq);
            float vv[4] = {va.x, va.y, va.z, va.w};
            unsigned short hh[4], ll[4];
            #pragma unroll
            for (int q = 0; q < 4; q++) {
                __nv_bfloat16 bh = __float2bfloat16(vv[q]);
                hh[q] = __bfloat16_as_ushort(bh);
                ll[q] = __bfloat16_as_ushort(__float2bfloat16(vv[q] - __bfloat162float(bh)));
            }
            *reinterpret_cast<uint2*>(&sAh[r*STR + kq]) =
                make_uint2((uint32_t)hh[0] | ((uint32_t)hh[1]<<16), (uint32_t)hh[2] | ((uint32_t)hh[3]<<16));
            *reinterpret_cast<uint2*>(&sAl[r*STR + kq]) =
                make_uint2((uint32_t)ll[0] | ((uint32_t)ll[1]<<16), (uint32_t)ll[2] | ((uint32_t)ll[3]<<16));
        }
        // B: 128 x 32 bf16 (hi & lo), [n][k] layout
        #pragma unroll
        for (int i = 0; i < 4; i++) {
            int idx = tid + i*256;
            int n = idx >> 3, kq = (idx & 7) * 4;
            uint2 vh = *reinterpret_cast<const uint2*>(Bhi + (size_t)(colb+n)*K + kc*32 + kq);
            uint2 vl = *reinterpret_cast<const uint2*>(Blo + (size_t)(colb+n)*K + kc*32 + kq);
            *reinterpret_cast<uint2*>(&sBh[n*STR + kq]) = vh;
            *reinterpret_cast<uint2*>(&sBl[n*STR + kq]) = vl;
        }
        __syncthreads();

        const uint32_t* pAh = reinterpret_cast<const uint32_t*>(sAh);
        const uint32_t* pAl = reinterpret_cast<const uint32_t*>(sAl);
        const uint32_t* pBh = reinterpret_cast<const uint32_t*>(sBh);
        const uint32_t* pBl = reinterpret_cast<const uint32_t*>(sBl);

        #pragma unroll
        for (int ks = 0; ks < 2; ks++) {
            uint32_t ah[2][4], al[2][4];
            #pragma unroll
            for (int mt = 0; mt < 2; mt++) {
                int rb = wm*32 + mt*16;
                int base = (rb+g)*STRW + ks*8 + t;
                int base8 = (rb+g+8)*STRW + ks*8 + t;
                ah[mt][0] = pAh[base];   ah[mt][1] = pAh[base8];
                ah[mt][2] = pAh[base+4]; ah[mt][3] = pAh[base8+4];
                al[mt][0] = pAl[base];   al[mt][1] = pAl[base8];
                al[mt][2] = pAl[base+4]; al[mt][3] = pAl[base8+4];
            }
            #pragma unroll
            for (int nt = 0; nt < 8; nt++) {
                int nb = wn*64 + nt*8;
                int bbase = (nb+g)*STRW + ks*8 + t;
                uint32_t bh0 = pBh[bbase], bh1 = pBh[bbase+4];
                uint32_t bl0 = pBl[bbase], bl1 = pBl[bbase+4];
                #pragma unroll
                for (int mt = 0; mt < 2; mt++) {
                    mma16816(acc[mt][nt], ah[mt], bh0, bh1);
                    mma16816(acc[mt][nt], ah[mt], bl0, bl1);
                    mma16816(acc[mt][nt], al[mt], bh0, bh1);
                }
            }
        }
        __syncthreads();
    }

    // epilogue
    #pragma unroll
    for (int mt = 0; mt < 2; mt++) {
        #pragma unroll
        for (int hh = 0; hh < 2; hh++) {
            int grow = row0 + wm*32 + mt*16 + g + hh*8;
            const float* na = nullptr; const float* nc = nullptr;
            if (mode == 1) {
                int e = grow;
                int nf = e >> 5;
                int bb = nf >> 11;
                int j = g_Eidx[e];
                na = &g_nA[nf*H_];
                nc = &g_nC[(bb*N_ + j)*H_];
            }
            #pragma unroll
            for (int nt = 0; nt < 8; nt++) {
                int cl = wn*64 + nt*8 + t*2;
                float d0 = acc[mt][nt][hh*2+0];
                float d1 = acc[mt][nt][hh*2+1];
                if (bias) { d0 += __ldg(&bias[colb+cl]); d1 += __ldg(&bias[colb+cl+1]); }
                if (mode == 1) {
                    d0 = fmaxf(d0 + na[cl] + nc[cl], 0.f);
                    d1 = fmaxf(d1 + na[cl+1] + nc[cl+1], 0.f);
                } else if (relu) {
                    d0 = fmaxf(d0, 0.f); d1 = fmaxf(d1, 0.f);
                }
                *reinterpret_cast<float2*>(C + (size_t)grow*ldc + colb + cl) = make_float2(d0, d1);
            }
        }
    }
}

// ---------------- row layernorm ----------------
__global__ void ln_rows_kernel(float* __restrict__ x, const float* __restrict__ g, const float* __restrict__ h, int M) {
    int row = blockIdx.x*blockDim.y + threadIdx.y;
    if (row >= M) return;
    int lane = threadIdx.x;
    float v[4]; float s = 0.f;
    #pragma unroll
    for (int r=0;r<4;r++) { v[r] = x[(size_t)row*H_ + lane + r*32]; s += v[r]; }
    #pragma unroll
    for (int off=16;off>0;off>>=1) s += __shfl_xor_sync(0xffffffffu, s, off);
    float mu = s * (1.f/H_);
    float ss = 0.f;
    #pragma unroll
    for (int r=0;r<4;r++) { float d = v[r]-mu; ss += d*d; }
    #pragma unroll
    for (int off=16;off>0;off>>=1) ss += __shfl_xor_sync(0xffffffffu, ss, off);
    float inv = 1.f / (sqrtf(ss*(1.f/(H_-1)) + EPSF) + EPSF);
    #pragma unroll
    for (int r=0;r<4;r++) {
        int c = lane + r*32;
        x[(size_t)row*H_ + c] = g[c]*(v[r]-mu)*inv + h[c];
    }
}

// ---------------- aggregate + residual LN ----------------
__global__ void aggregate_kernel(const float* __restrict__ mask,
                                 const float* __restrict__ g0, const float* __restrict__ h0) {
    __shared__ float red[H_];
    int n = blockIdx.x, o = threadIdx.x;
    int b = n / N_;
    float mi = mask[n];
    float s = 0.f;
    for (int k = 0; k < K_; k++) {
        int e = n*K_ + k;
        int j = g_Eidx[e];
        float ma = mi * mask[b*N_+j];
        s += g_t0[(size_t)e*H_ + o] * ma;
    }
    float x = g_hV[n*H_+o] + s * (1.f/30.f);
    float mu = block_sum128(x, red) * (1.f/H_);
    float dv = x - mu;
    float var = block_sum128(dv*dv, red) * (1.f/(H_-1));
    g_hV[n*H_+o] = g0[o]*dv/(sqrtf(var+EPSF)+EPSF) + h0[o];
}

// ---------------- residual FFN LN + mask ----------------
__global__ void resln_kernel(float* __restrict__ dst, const float* __restrict__ mask,
                             const float* __restrict__ g1, const float* __restrict__ h1) {
    __shared__ float red[H_];
    int n = blockIdx.x, o = threadIdx.x;
    float x = g_hV[n*H_+o] + g_dh[n*H_+o];
    float mu = block_sum128(x, red) * (1.f/H_);
    float dv = x - mu;
    float var = block_sum128(dv*dv, red) * (1.f/(H_-1));
    float y = g1[o]*dv/(sqrtf(var+EPSF)+EPSF) + h1[o];
    dst[n*H_+o] = mask[n]*y;
}

// ---------------- host ----------------
extern "C" void kernel_launch(void* const* d_in, const int* in_sizes, int n_in,
                              void* d_out, int out_size) {
    const float* X    = (const float*)d_in[0];
    const float* mask = (const float*)d_in[1];
    const float* Wn   = (const float*)d_in[2];
    const float* bn   = (const float*)d_in[3];
    const float* gn   = (const float*)d_in[4];
    const float* hn   = (const float*)d_in[5];
    const float* We   = (const float*)d_in[6];
    const float* be   = (const float*)d_in[7];
    const float* ge   = (const float*)d_in[8];
    const float* he   = (const float*)d_in[9];
    const float* Wv   = (const float*)d_in[10];
    const float* bv   = (const float*)d_in[11];
    const float* Wq   = (const float*)d_in[12];
    const float* bq   = (const float*)d_in[13];
    const float* lW1  = (const float*)d_in[14];
    const float* lb1  = (const float*)d_in[15];
    const float* lW2  = (const float*)d_in[16];
    const float* lb2  = (const float*)d_in[17];
    const float* lW3  = (const float*)d_in[18];
    const float* lb3  = (const float*)d_in[19];
    const float* lWi  = (const float*)d_in[20];
    const float* lbi  = (const float*)d_in[21];
    const float* lWo  = (const float*)d_in[22];
    const float* lbo  = (const float*)d_in[23];
    const float* lg0  = (const float*)d_in[24];
    const float* lh0  = (const float*)d_in[25];
    const float* lg1  = (const float*)d_in[26];
    const float* lh1  = (const float*)d_in[27];

    float *t0, *t1, *hE, *hV, *ff, *dh, *Ebuf;
    __nv_bfloat16 *wh, *wl;
    cudaGetSymbolAddress((void**)&t0,   g_t0);
    cudaGetSymbolAddress((void**)&t1,   g_t1);
    cudaGetSymbolAddress((void**)&hE,   g_hE);
    cudaGetSymbolAddress((void**)&hV,   g_hV);
    cudaGetSymbolAddress((void**)&ff,   g_ff);
    cudaGetSymbolAddress((void**)&dh,   g_dh);
    cudaGetSymbolAddress((void**)&Ebuf, g_Ebuf);
    cudaGetSymbolAddress((void**)&wh,   g_wh);
    cudaGetSymbolAddress((void**)&wl,   g_wl);
    float* nA; cudaGetSymbolAddress((void**)&nA, g_nA);
    float* nC; cudaGetSymbolAddress((void**)&nC, g_nC);

    auto prep = [&](const float* W, size_t off, int Ksrc, int N, int Kpad) {
        int tot = N*Kpad;
        prep_w<<<(tot+255)/256, 256>>>(W, wh+off, wl+off, Ksrc, N, Kpad);
    };
    auto gemm = [&](const float* A, size_t woff, const float* bias, float* C,
                    int M, int N, int Kd, int mode, int relu) {
        dim3 grid(N/128, M/128);
        mma_gemm<<<grid, 256>>>(A, wh+woff, wl+woff, bias, C, Kd, N, mode, relu);
    };

    // weight prep
    prep(We, OFF_WE, 39, 128, 64);
    prep(Wq, OFF_WQ, 128, 128, 128);
    for (int l = 0; l < L_; l++) {
        size_t base = OFF_L0 + (size_t)l*LSTRIDE;
        prep(lW1 + (size_t)l*384*128,             base + OW1A, 128, 128, 128);
        prep(lW1 + (size_t)l*384*128 + 128*128,   base + OW1E, 128, 128, 128);
        prep(lW1 + (size_t)l*384*128 + 256*128,   base + OW1C, 128, 128, 128);
        prep(lW2 + (size_t)l*128*128,             base + OW2,  128, 128, 128);
        prep(lW3 + (size_t)l*128*128,             base + OW3,  128, 128, 128);
        prep(lWi + (size_t)l*128*512,             base + OWI,  128, 512, 128);
        prep(lWo + (size_t)l*512*128,             base + OWO,  512, 128, 512);
    }

    // Phase A
    knn_kernel<<<NNODE, 256>>>(X, mask);
    frames_kernel<<<(NNODE+255)/256, 256>>>(X);
    node_init_kernel<<<NNODE, 128>>>(Wn, bn, gn, hn, Wv, bv);
    edge_feat_kernel<<<(NE+255)/256, 256>>>(X);
    gemm(Ebuf, OFF_WE, be, t0, NE, 128, 64, 0, 0);
    {
        dim3 blk(32, 8);
        ln_rows_kernel<<<(NE+7)/8, blk>>>(t0, ge, he, NE);
    }
    gemm(t0, OFF_WQ, bq, hE, NE, 128, 128, 0, 0);

    // Phase B
    for (int l = 0; l < L_; l++) {
        size_t base = OFF_L0 + (size_t)l*LSTRIDE;
        gemm(hV, base + OW1A, lb1 + l*H_, nA, NNODE, 128, 128, 0, 0);
        gemm(hV, base + OW1C, nullptr,    nC, NNODE, 128, 128, 0, 0);
        gemm(hE, base + OW1E, nullptr,    t0, NE,    128, 128, 1, 0);   // combine fused
        gemm(t0, base + OW2,  lb2 + l*H_, t1, NE,    128, 128, 0, 1);
        gemm(t1, base + OW3,  lb3 + l*H_, t0, NE,    128, 128, 0, 0);
        aggregate_kernel<<<NNODE, H_>>>(mask, lg0 + l*H_, lh0 + l*H_);
        gemm(hV, base + OWI, lbi + l*DFF_, ff, NNODE, 512, 128, 0, 1);
        gemm(ff, base + OWO, lbo + l*H_,   dh, NNODE, 128, 512, 0, 0);
        float* dst = (l == L_-1) ? (float*)d_out : hV;
        resln_kernel<<<NNODE, H_>>>(dst, mask, lg1 + l*H_, lh1 + l*H_);
    }
}